// round 15
// baseline (speedup 1.0000x reference)
#include <cuda_runtime.h>
#include <cstdint>

// ---------------------------------------------------------------------------
// EfficientAttention_Mapping: B=256, 2N=4096 (two halves of N=2048), D=3, DK=64
//
// Exact reformulation accumulated per (b,half):
//   qbar[j] = sum_n exp(lq[n,j]) / sum_j' exp(lq[n,j'])
//   kden[j] = sum_n exp(lk[n,j])          [bk dropped: it cancels in knum/kden]
//   M[j][e] = sum_n exp(lk[n,j]) * x[n,e]
// then
//   knum[j][d] = sum_e M[j][e]*Wv[e,d] + bv[d]*kden[j]
//   out_half[d] = (1/N) * sum_j qbar[j] * knum[j][d] / kden[j]
//
// Round 13: role-split CTAs, each with the 8-j-per-thread layout (8-thread
// groups, 32 groups/CTA) so the per-row fixed costs (LDS, butterfly, rcp)
// amortize over twice as many j-cells: ~25% fewer instructions total.
// bk is dropped from the k side (exact: scales kden and M identically).
// ---------------------------------------------------------------------------

typedef unsigned long long ull;

__device__ __forceinline__ ull pack2(float lo, float hi) {
    ull r; asm("mov.b64 %0, {%1, %2};" : "=l"(r) : "f"(lo), "f"(hi)); return r;
}
__device__ __forceinline__ void unpack2(ull v, float& lo, float& hi) {
    asm("mov.b64 {%0, %1}, %2;" : "=f"(lo), "=f"(hi) : "l"(v));
}
__device__ __forceinline__ ull fma2(ull a, ull b, ull c) {
    ull d; asm("fma.rn.f32x2 %0, %1, %2, %3;" : "=l"(d) : "l"(a), "l"(b), "l"(c)); return d;
}
__device__ __forceinline__ ull add2(ull a, ull b) {
    ull d; asm("add.rn.f32x2 %0, %1, %2;" : "=l"(d) : "l"(a), "l"(b)); return d;
}
__device__ __forceinline__ ull mul2(ull a, ull b) {
    ull d; asm("mul.rn.f32x2 %0, %1, %2;" : "=l"(d) : "l"(a), "l"(b)); return d;
}
__device__ __forceinline__ float ex2f(float x) {
    float y; asm("ex2.approx.ftz.f32 %0, %1;" : "=f"(y) : "f"(x)); return y;
}
__device__ __forceinline__ float rcpf(float x) {
    float y; asm("rcp.approx.ftz.f32 %0, %1;" : "=f"(y) : "f"(x)); return y;
}
__device__ __forceinline__ ull ex2pair(ull v) {
    float a, b; unpack2(v, a, b);
    return pack2(ex2f(a), ex2f(b));
}

#define LOG2E_F 1.4426950408889634f

// Scratch: 2048 row-blocks x 320 partials (qbar[64], M0[64], M1[64], M2[64], kden[64])
__device__ float g_part[2048 * 320];
__device__ int   g_cnt[256];   // zero-init; counts 16 CTAs/batch; reset each replay

__global__ __launch_bounds__(256, 3)
void ea_split8_kernel(const float* __restrict__ xin,
                      const float* __restrict__ Wq, const float* __restrict__ bq,
                      const float* __restrict__ Wk, const float* __restrict__ bk,
                      const float* __restrict__ Wv, const float* __restrict__ bv,
                      float* __restrict__ out)
{
    __shared__ ull         xs2[512 * 3];       // 12 KB: x chunk, value duplicated per pair
    __shared__ ulonglong2  wsu[2][4][8];       // 1 KB: this role's weight pairs (log2e-scaled)
    __shared__ float       red[5][8][64];      // 10 KB
    __shared__ int         s_old;
    __shared__ float       fsh[2][3];
    __shared__ float       ohalf[2][3];

    const int tid  = threadIdx.x;
    const int blk  = blockIdx.x;               // 0..4095
    const int  w3  = blk & 7;                  // role interleave (kept from R12)
    const bool isq = w3 < 4;
    const int  rb  = (blk >> 3) * 4 + (w3 & 3);  // row-block 0..2047

    // --- stage x chunk as duplicated pairs ---
    {
        const float* src = xin + (size_t)rb * 1536;
        #pragma unroll
        for (int i = tid; i < 1536; i += 256) {
            const float v = src[i];
            xs2[i] = pack2(v, v);
        }
    }

    // --- stage this role's weights: wsu[sp][u][c] for j0=c+16u, j1=j0+8
    // sp0: (W row0 pair, W row1 pair)   sp1: (W row2 pair, bias pair)
    // k role: bias = 0 (bk cancels exactly in the column softmax).
    {
        const float* W = isq ? Wq : Wk;
        float4* wf = reinterpret_cast<float4*>(&wsu[0][0][0]);
        if (tid < 64) {
            int c  = tid & 7;
            int u  = (tid >> 3) & 3;
            int sp = tid >> 5;
            int j0 = c + 16 * u, j1 = j0 + 8;
            float a, b, cc, d;
            if (sp == 0) { a = W[j0];       b = W[j1];       cc = W[64 + j0];        d = W[64 + j1]; }
            else         { a = W[128 + j0]; b = W[128 + j1]; cc = isq ? bq[j0] : 0.f; d = isq ? bq[j1] : 0.f; }
            wf[tid] = make_float4(a * LOG2E_F, b * LOG2E_F, cc * LOG2E_F, d * LOG2E_F);
        }
    }
    __syncthreads();

    const int c    = tid & 7;      // j-slice within group (0..7)
    const int g    = tid >> 3;     // group = row lane (32 groups, 16 rows each)
    const int lane = tid & 31;
    const int w    = tid >> 5;

    const ull Z = pack2(0.0f, 0.0f);

    if (isq) {
        // =================== q role: qbar, 8 j's/thread ===================
        ulonglong2 w01[4], w2b[4];
        #pragma unroll
        for (int u = 0; u < 4; ++u) { w01[u] = wsu[0][u][c]; w2b[u] = wsu[1][u][c]; }

        ull qb2[4] = {Z, Z, Z, Z};

        #pragma unroll 1
        for (int it = 0; it < 8; ++it) {
            const int rA = g + (it << 5);
            const int rB = rA + 256;
            const ull XA0 = xs2[rA * 3 + 0], XA1 = xs2[rA * 3 + 1], XA2 = xs2[rA * 3 + 2];
            const ull XB0 = xs2[rB * 3 + 0], XB1 = xs2[rB * 3 + 1], XB2 = xs2[rB * 3 + 2];

            ull eqA[4], eqB[4];
            #pragma unroll
            for (int u = 0; u < 4; ++u) {
                ull lq = fma2(XA0, w01[u].x, fma2(XA1, w01[u].y, fma2(XA2, w2b[u].x, w2b[u].y)));
                eqA[u] = ex2pair(lq);
            }
            #pragma unroll
            for (int u = 0; u < 4; ++u) {
                ull lq = fma2(XB0, w01[u].x, fma2(XB1, w01[u].y, fma2(XB2, w2b[u].x, w2b[u].y)));
                eqB[u] = ex2pair(lq);
            }

            // dual-row packed butterfly over the 8-thread group (3 shfl)
            ull tA = add2(add2(eqA[0], eqA[1]), add2(eqA[2], eqA[3]));
            ull tB = add2(add2(eqB[0], eqB[1]), add2(eqB[2], eqB[3]));
            float al, ah, bl, bh;
            unpack2(tA, al, ah);
            unpack2(tB, bl, bh);
            ull s2 = pack2(al + ah, bl + bh);
            s2 = add2(s2, __shfl_xor_sync(0xffffffffu, s2, 1));
            s2 = add2(s2, __shfl_xor_sync(0xffffffffu, s2, 2));
            s2 = add2(s2, __shfl_xor_sync(0xffffffffu, s2, 4));
            float sA, sB;
            unpack2(s2, sA, sB);
            const ull RA = pack2(rcpf(sA), rcpf(sA));
            const ull RB = pack2(rcpf(sB), rcpf(sB));

            #pragma unroll
            for (int u = 0; u < 4; ++u) {
                qb2[u] = fma2(eqA[u], RA, qb2[u]);
                qb2[u] = fma2(eqB[u], RB, qb2[u]);
            }
        }

        // combine the 4 groups within each warp (lane bits 3,4)
        #pragma unroll
        for (int u = 0; u < 4; ++u) {
            qb2[u] = add2(qb2[u], __shfl_xor_sync(0xffffffffu, qb2[u], 8));
            qb2[u] = add2(qb2[u], __shfl_xor_sync(0xffffffffu, qb2[u], 16));
        }
        if (lane < 8) {
            #pragma unroll
            for (int u = 0; u < 4; ++u) {
                const int j0 = lane + 16 * u, j1 = j0 + 8;
                float a, b;
                unpack2(qb2[u], a, b);
                red[0][w][j0] = a; red[0][w][j1] = b;
            }
        }
        __syncthreads();

        if (tid < 64) {
            float s = 0.0f;
            #pragma unroll
            for (int ww = 0; ww < 8; ++ww) s += red[0][ww][tid];
            g_part[(size_t)rb * 320 + tid] = s;
        }
    } else {
        // =================== k role: M, kden — 8 j's/thread, no bias ===================
        ulonglong2 w01[4];
        ull w2[4];
        #pragma unroll
        for (int u = 0; u < 4; ++u) { w01[u] = wsu[0][u][c]; w2[u] = wsu[1][u][c].x; }

        ull M0[4] = {Z, Z, Z, Z}, M1[4] = {Z, Z, Z, Z}, M2a[4] = {Z, Z, Z, Z}, kd2[4] = {Z, Z, Z, Z};

        #pragma unroll 1
        for (int it = 0; it < 8; ++it) {
            const int rA = g + (it << 5);
            const int rB = rA + 256;
            {
                const ull X0 = xs2[rA * 3 + 0], X1 = xs2[rA * 3 + 1], X2 = xs2[rA * 3 + 2];
                #pragma unroll
                for (int u = 0; u < 4; ++u) {
                    ull lk = fma2(X0, w01[u].x, fma2(X1, w01[u].y, mul2(X2, w2[u])));
                    ull ek = ex2pair(lk);
                    kd2[u] = add2(kd2[u], ek);
                    M0[u]  = fma2(ek, X0, M0[u]);
                    M1[u]  = fma2(ek, X1, M1[u]);
                    M2a[u] = fma2(ek, X2, M2a[u]);
                }
            }
            {
                const ull X0 = xs2[rB * 3 + 0], X1 = xs2[rB * 3 + 1], X2 = xs2[rB * 3 + 2];
                #pragma unroll
                for (int u = 0; u < 4; ++u) {
                    ull lk = fma2(X0, w01[u].x, fma2(X1, w01[u].y, mul2(X2, w2[u])));
                    ull ek = ex2pair(lk);
                    kd2[u] = add2(kd2[u], ek);
                    M0[u]  = fma2(ek, X0, M0[u]);
                    M1[u]  = fma2(ek, X1, M1[u]);
                    M2a[u] = fma2(ek, X2, M2a[u]);
                }
            }
        }

        #pragma unroll
        for (int u = 0; u < 4; ++u) {
            M0[u]  = add2(M0[u],  __shfl_xor_sync(0xffffffffu, M0[u],  8));
            M0[u]  = add2(M0[u],  __shfl_xor_sync(0xffffffffu, M0[u],  16));
            M1[u]  = add2(M1[u],  __shfl_xor_sync(0xffffffffu, M1[u],  8));
            M1[u]  = add2(M1[u],  __shfl_xor_sync(0xffffffffu, M1[u],  16));
            M2a[u] = add2(M2a[u], __shfl_xor_sync(0xffffffffu, M2a[u], 8));
            M2a[u] = add2(M2a[u], __shfl_xor_sync(0xffffffffu, M2a[u], 16));
            kd2[u] = add2(kd2[u], __shfl_xor_sync(0xffffffffu, kd2[u], 8));
            kd2[u] = add2(kd2[u], __shfl_xor_sync(0xffffffffu, kd2[u], 16));
        }

        if (lane < 8) {
            #pragma unroll
            for (int u = 0; u < 4; ++u) {
                const int j0 = lane + 16 * u, j1 = j0 + 8;
                float a, b;
                unpack2(M0[u],  a, b); red[1][w][j0] = a; red[1][w][j1] = b;
                unpack2(M1[u],  a, b); red[2][w][j0] = a; red[2][w][j1] = b;
                unpack2(M2a[u], a, b); red[3][w][j0] = a; red[3][w][j1] = b;
                unpack2(kd2[u], a, b); red[4][w][j0] = a; red[4][w][j1] = b;
            }
        }
        __syncthreads();

        {
            const int vi  = 64 + tid;          // 64..319
            const int acc = vi >> 6, j = vi & 63;
            float s = 0.0f;
            #pragma unroll
            for (int ww = 0; ww < 8; ++ww) s += red[acc][ww][j];
            g_part[(size_t)rb * 320 + vi] = s;
        }
    }

    // ---------------- fused finalize: last of 16 CTAs per batch ----------------
    const int bb = rb >> 3;
    __syncthreads();
    if (tid == 0) {
        __threadfence();
        s_old = atomicAdd(&g_cnt[bb], 1);
    }
    __syncthreads();
    if (s_old != 15) return;

    __threadfence();

    const int j = tid;
    if (j < 64) {
        for (int h = 0; h < 2; ++h) {
            float qb = 0.0f, m0 = 0.0f, m1 = 0.0f, m2 = 0.0f, kd = 0.0f;
            const size_t base = (size_t)(bb * 8 + h * 4) * 320;
            #pragma unroll
            for (int s = 0; s < 4; ++s) {
                const float* p = g_part + base + (size_t)s * 320;
                qb += p[j];
                m0 += p[64 + j];
                m1 += p[128 + j];
                m2 += p[192 + j];
                kd += p[256 + j];
            }
            const float rkd = 1.0f / kd;
            float t[3];
            #pragma unroll
            for (int d = 0; d < 3; ++d) {
                const float kn = m0 * Wv[0 * 3 + d] + m1 * Wv[1 * 3 + d]
                               + m2 * Wv[2 * 3 + d] + bv[d] * kd;
                t[d] = qb * (kn * rkd);
            }
            #pragma unroll
            for (int o = 16; o >= 1; o >>= 1) {
                t[0] += __shfl_xor_sync(0xffffffffu, t[0], o);
                t[1] += __shfl_xor_sync(0xffffffffu, t[1], o);
                t[2] += __shfl_xor_sync(0xffffffffu, t[2], o);
            }
            const int ww = j >> 5;
            if ((j & 31) == 0) { fsh[ww][0] = t[0]; fsh[ww][1] = t[1]; fsh[ww][2] = t[2]; }
            __syncwarp(0xffffffffu);
            if (h == 0) {
                __syncthreads();
                if (j == 0)
                    for (int d = 0; d < 3; ++d)
                        ohalf[0][d] = (fsh[0][d] + fsh[1][d]) * (1.0f / 2048.0f);
                __syncthreads();
            }
        }
    } else {
        __syncthreads();
        __syncthreads();
    }
    __syncthreads();
    if (j == 0) {
        const float oh1_0 = (fsh[0][0] + fsh[1][0]) * (1.0f / 2048.0f);
        const float oh1_1 = (fsh[0][1] + fsh[1][1]) * (1.0f / 2048.0f);
        const float oh1_2 = (fsh[0][2] + fsh[1][2]) * (1.0f / 2048.0f);
        const float a0 = 0.5f * (ohalf[0][0] + oh1_0);
        const float a1 = 0.5f * (ohalf[0][1] + oh1_1);
        const float a2 = 0.5f * (ohalf[0][2] + oh1_2);
        const float inv = rsqrtf(a0 * a0 + a1 * a1 + a2 * a2);
        out[bb * 3 + 0] = a0 * inv;
        out[bb * 3 + 1] = a1 * inv;
        out[bb * 3 + 2] = a2 * inv;
        g_cnt[bb] = 0;                  // reset for next graph replay
    }
}

// ---------------------------------------------------------------------------
extern "C" void kernel_launch(void* const* d_in, const int* in_sizes, int n_in,
                              void* d_out, int out_size)
{
    const float* xin = (const float*)d_in[0];
    const float* Wq  = (const float*)d_in[1];
    const float* bq  = (const float*)d_in[2];
    const float* Wk  = (const float*)d_in[3];
    const float* bk  = (const float*)d_in[4];
    const float* Wv  = (const float*)d_in[5];
    const float* bv  = (const float*)d_in[6];
    float* out = (float*)d_out;

    ea_split8_kernel<<<4096, 256>>>(xin, Wq, bq, Wk, bk, Wv, bv, out);
}